// round 2
// baseline (speedup 1.0000x reference)
#include <cuda_runtime.h>

// Problem constants
#define NROWS 8192          // 2*N rows after the concat
#define HID   256           // hidden width (= 2F = H)
#define RPB   16            // rows per block
#define KT    64            // k-tile width for shared weight tiles
#define NCOORD (4096 * 6)

#define SMEM_FLOATS (2 * RPB * HID + HID * (KT + 1))
#define SMEM_BYTES  (SMEM_FLOATS * sizeof(float))

// Ping-pong activation scratch (allocation-free: __device__ globals)
__device__ float g_bufA[NROWS * HID];
__device__ float g_bufB[NROWS * HID];

// ---------------------------------------------------------------------------
// Fourier feature kernel: out[m, f] = sin(2pi * x_m . B[:,f]), out[m,128+f]=cos
// Rows 0..4095 use coords[:, 0:3]; rows 4096..8191 use coords[:, 3:6].
// Uses precise sinf/cosf (args up to ~35 rad); count is tiny (1M sincos).
// ---------------------------------------------------------------------------
__global__ void fourier_kernel(const float* __restrict__ coords,
                               const float* __restrict__ B,
                               float* __restrict__ out) {
    int m = blockIdx.x;       // 0..8191
    int f = threadIdx.x;      // 0..127
    float x0, x1, x2;
    if (m < 4096) {
        const float* c = coords + m * 6;
        x0 = c[0]; x1 = c[1]; x2 = c[2];
    } else {
        const float* c = coords + (m - 4096) * 6;
        x0 = c[3]; x1 = c[4]; x2 = c[5];
    }
    float p = x0 * __ldg(&B[f]) + x1 * __ldg(&B[128 + f]) + x2 * __ldg(&B[256 + f]);
    p *= 6.283185307179586f;
    out[m * HID + f]       = sinf(p);
    out[m * HID + 128 + f] = cosf(p);
}

// ---------------------------------------------------------------------------
// Fused layer kernel.
//   S[m,h]   = sum_k sin(X[m,k] * Wsin[h,k])          (the sin_layer)
//   if HAS_MM: Y[m,j] = sin( sum_h S[m,h]*W1[j,h] + b1[j] )
//   else:      Y[m,h] = S[m,h]
// Block: 256 threads, RPB rows. Thread t owns output column t for all RPB rows.
// Weight tiles staged in shared with stride KT+1=65 -> conflict-free
// (bank = (t*65 + k) % 32 = (t + k) % 32, distinct across lanes).
// ---------------------------------------------------------------------------
template <bool HAS_MM>
__global__ void layer_kernel(const float* __restrict__ X,
                             const float* __restrict__ Wsin,
                             const float* __restrict__ W1,
                             const float* __restrict__ b1,
                             float* __restrict__ Y) {
    extern __shared__ float smem[];
    float* sX = smem;                  // RPB * HID
    float* sS = smem + RPB * HID;      // RPB * HID
    float* sW = smem + 2 * RPB * HID;  // HID * (KT+1)

    const int tid  = threadIdx.x;      // 0..255
    const int row0 = blockIdx.x * RPB;

    // Stage the block's input rows (coalesced).
    for (int i = tid; i < RPB * HID; i += 256)
        sX[i] = X[row0 * HID + i];
    __syncthreads();

    // ---- Phase A: sin_layer, accumulate RPB rows per thread ----
    float acc[RPB];
#pragma unroll
    for (int r = 0; r < RPB; r++) acc[r] = 0.f;

    for (int k0 = 0; k0 < HID; k0 += KT) {
        // Stage Wsin[:, k0:k0+KT] (coalesced global, padded shared).
        for (int i = tid; i < HID * KT; i += 256) {
            int h = i / KT, k = i % KT;
            sW[h * (KT + 1) + k] = Wsin[h * HID + k0 + k];
        }
        __syncthreads();
        for (int k = 0; k < KT; k++) {
            float w = sW[tid * (KT + 1) + k];   // conflict-free
#pragma unroll
            for (int r = 0; r < RPB; r++)
                acc[r] += __sinf(sX[r * HID + k0 + k] * w);  // sX read = broadcast
        }
        __syncthreads();
    }

    if (HAS_MM) {
        // Publish S to shared for the matmul.
#pragma unroll
        for (int r = 0; r < RPB; r++) sS[r * HID + tid] = acc[r];

        const float bias = b1[tid];
        float acc2[RPB];
#pragma unroll
        for (int r = 0; r < RPB; r++) acc2[r] = bias;
        __syncthreads();

        // ---- Phase B: Y = sin(S @ W1^T + b) ----
        for (int h0 = 0; h0 < HID; h0 += KT) {
            for (int i = tid; i < HID * KT; i += 256) {
                int j = i / KT, h = i % KT;
                sW[j * (KT + 1) + h] = W1[j * HID + h0 + h];
            }
            __syncthreads();
            for (int h = 0; h < KT; h++) {
                float w = sW[tid * (KT + 1) + h];
#pragma unroll
                for (int r = 0; r < RPB; r++)
                    acc2[r] += sS[r * HID + h0 + h] * w;
            }
            __syncthreads();
        }
#pragma unroll
        for (int r = 0; r < RPB; r++)
            Y[(row0 + r) * HID + tid] = __sinf(acc2[r]);
    } else {
#pragma unroll
        for (int r = 0; r < RPB; r++)
            Y[(row0 + r) * HID + tid] = acc[r];
    }
}

// Append coords to the output (tuple element #2).
__global__ void copy_kernel(const float* __restrict__ src,
                            float* __restrict__ dst, int n) {
    int i = blockIdx.x * blockDim.x + threadIdx.x;
    if (i < n) dst[i] = src[i];
}

extern "C" void kernel_launch(void* const* d_in, const int* in_sizes, int n_in,
                              void* d_out, int out_size) {
    const float* coords = (const float*)d_in[0];  // (4096, 6)
    const float* B      = (const float*)d_in[1];  // (3, 128)
    const float* w0     = (const float*)d_in[2];  // (256, 256)
    const float* ws     = (const float*)d_in[3];  // (3, 256, 256)
    const float* w_last = (const float*)d_in[4];  // (256, 256)
    const float* w1     = (const float*)d_in[5];  // (4, 256, 256)
    const float* b1     = (const float*)d_in[6];  // (4, 256)
    float* out = (float*)d_out;

    float *bufA, *bufB;
    cudaGetSymbolAddress((void**)&bufA, g_bufA);
    cudaGetSymbolAddress((void**)&bufB, g_bufB);

    cudaFuncSetAttribute(layer_kernel<true>,
                         cudaFuncAttributeMaxDynamicSharedMemorySize, (int)SMEM_BYTES);
    cudaFuncSetAttribute(layer_kernel<false>,
                         cudaFuncAttributeMaxDynamicSharedMemorySize, (int)SMEM_BYTES);

    const int grid = NROWS / RPB;  // 512 blocks

    fourier_kernel<<<NROWS, 128>>>(coords, B, bufA);
    // Layer 0: sin_layer(w0) -> sin(.@w1[0]^T + b1[0])
    layer_kernel<true><<<grid, 256, SMEM_BYTES>>>(bufA, w0, w1, b1, bufB);
    // Layers 1..3: sin_layer(ws[i-1]) -> sin(.@w1[i]^T + b1[i])
    layer_kernel<true><<<grid, 256, SMEM_BYTES>>>(bufB, ws,                w1 + 1 * 65536, b1 + 256, bufA);
    layer_kernel<true><<<grid, 256, SMEM_BYTES>>>(bufA, ws + 1 * 65536,   w1 + 2 * 65536, b1 + 512, bufB);
    layer_kernel<true><<<grid, 256, SMEM_BYTES>>>(bufB, ws + 2 * 65536,   w1 + 3 * 65536, b1 + 768, bufA);
    // Final sin_layer(w_last), straight to output.
    layer_kernel<false><<<grid, 256, SMEM_BYTES>>>(bufA, w_last, nullptr, nullptr, out);
    // Tuple element 2: coords passthrough.
    copy_kernel<<<(NCOORD + 255) / 256, 256>>>(coords, out + NROWS * HID, NCOORD);
}

// round 4
// speedup vs baseline: 5.4656x; 5.4656x over previous
#include <cuda_runtime.h>
#include <cuda_bf16.h>
#include <cstdint>

// ---------------- problem constants ----------------
#define MROWS 8192          // 2*N rows
#define HID   256
#define K1    1280          // sin_layer expanded K: [x_hi, x_hi, x_lo, x^3, x^5]
#define K2    768           // matmul expanded K:    [s_hi, s_hi, s_lo]
#define NCOORD (4096 * 6)

#define TILE_M 128
#define TILE_N 128
#define KC     64                // K chunk: 64 bf16 = 128B rows
#define STAGE_BYTES 32768        // A tile 16KB + B tile 16KB
#define SMEM_TOTAL  (2 * STAGE_BYTES)

// ---------------- device scratch (allocation-free) ----------------
__device__ __align__(256) __nv_bfloat16 g_Xexp[(size_t)MROWS * K1];
__device__ __align__(256) __nv_bfloat16 g_Sexp[(size_t)MROWS * K2];
__device__ __align__(256) __nv_bfloat16 g_Wsin[(size_t)5 * HID * K1];
__device__ __align__(256) __nv_bfloat16 g_Wmm [(size_t)4 * HID * K2];

// ---------------- helpers ----------------
__device__ __forceinline__ uint32_t smem_u32(const void* p) {
    uint32_t a;
    asm("{ .reg .u64 t; cvta.to.shared.u64 t, %1; cvt.u32.u64 %0, t; }" : "=r"(a) : "l"(p));
    return a;
}
__device__ __forceinline__ uint32_t bf2u(float a, float b) {
    __nv_bfloat162 t = __floats2bfloat162_rn(a, b);
    return *reinterpret_cast<uint32_t*>(&t);
}

// ---------------- weight expansion kernels ----------------
// sin weights: slots [w_hi, w_lo, w_hi, -w^3/6, w^5/120]
__global__ void prep_sin_kernel(const float* __restrict__ w0, const float* __restrict__ ws,
                                const float* __restrict__ w_last, __nv_bfloat16* __restrict__ out) {
    int l = blockIdx.y;
    int idx = blockIdx.x * 256 + threadIdx.x;       // 0..65535
    const float* src = (l == 0) ? w0 : (l <= 3 ? ws + (l - 1) * 65536 : w_last);
    float w = src[idx];
    int h = idx >> 8, k = idx & 255;
    __nv_bfloat16* o = out + (size_t)l * HID * K1 + (size_t)h * K1 + k;
    float hi = __bfloat162float(__float2bfloat16_rn(w));
    float lo = w - hi;
    float ww = w * w;
    o[0]    = __float2bfloat16_rn(hi);
    o[256]  = __float2bfloat16_rn(lo);
    o[512]  = __float2bfloat16_rn(hi);
    o[768]  = __float2bfloat16_rn(-w * ww * (1.0f / 6.0f));
    o[1024] = __float2bfloat16_rn(w * ww * ww * (1.0f / 120.0f));
}
// matmul weights: slots [w_hi, w_lo, w_hi]
__global__ void prep_mm_kernel(const float* __restrict__ w1, __nv_bfloat16* __restrict__ out) {
    int l = blockIdx.y;
    int idx = blockIdx.x * 256 + threadIdx.x;
    float w = w1[(size_t)l * 65536 + idx];
    int h = idx >> 8, k = idx & 255;
    __nv_bfloat16* o = out + (size_t)l * HID * K2 + (size_t)h * K2 + k;
    float hi = __bfloat162float(__float2bfloat16_rn(w));
    float lo = w - hi;
    o[0]   = __float2bfloat16_rn(hi);
    o[256] = __float2bfloat16_rn(lo);
    o[512] = __float2bfloat16_rn(hi);
}

// ---------------- Fourier features -> expanded activations ----------------
__device__ __forceinline__ void write5(__nv_bfloat16* r, int j, float v) {
    float hi = __bfloat162float(__float2bfloat16_rn(v));
    float lo = v - hi;
    float vv = v * v;
    r[j]        = __float2bfloat16_rn(hi);
    r[256 + j]  = __float2bfloat16_rn(hi);
    r[512 + j]  = __float2bfloat16_rn(lo);
    r[768 + j]  = __float2bfloat16_rn(v * vv);
    r[1024 + j] = __float2bfloat16_rn(v * vv * vv);
}
__global__ void fourier_kernel(const float* __restrict__ coords, const float* __restrict__ B,
                               __nv_bfloat16* __restrict__ X) {
    int m = blockIdx.x;       // 0..8191
    int f = threadIdx.x;      // 0..127
    float x0, x1, x2;
    if (m < 4096) {
        const float* c = coords + m * 6;
        x0 = c[0]; x1 = c[1]; x2 = c[2];
    } else {
        const float* c = coords + (m - 4096) * 6;
        x0 = c[3]; x1 = c[4]; x2 = c[5];
    }
    float p = x0 * __ldg(&B[f]) + x1 * __ldg(&B[128 + f]) + x2 * __ldg(&B[256 + f]);
    p *= 6.283185307179586f;
    __nv_bfloat16* r = X + (size_t)m * K1;
    write5(r, f, sinf(p));
    write5(r, 128 + f, cosf(p));
}

// ---------------- HMMA GEMM with fused epilogue ----------------
// D[m,n] = sum_k A[m,k]*B[n,k]  (both K-major), fp32 accum.
// EPI 0: 3-slot split of D -> Sexp (K2 layout)
// EPI 1: y = sin(D + bias[n]) -> 5-slot expansion -> Xexp (K1 layout)
// EPI 2: fp32 D -> out
template <int KTOT, int EPI>
__global__ __launch_bounds__(256, 1)
void gemm_kernel(const __nv_bfloat16* __restrict__ A, const __nv_bfloat16* __restrict__ Bw,
                 const float* __restrict__ bias, void* __restrict__ outp) {
    extern __shared__ char smem[];
    const uint32_t sb = smem_u32(smem);
    const int tid = threadIdx.x;
    const int lane = tid & 31;
    const int wid = tid >> 5;
    const int warp_m = wid & 1;     // 0..1 : 64-row slab
    const int warp_n = wid >> 1;    // 0..3 : 32-col slab
    const int m0 = blockIdx.x * TILE_M;
    const int n0 = blockIdx.y * TILE_N;

    float acc[4][4][4];
#pragma unroll
    for (int i = 0; i < 4; i++)
#pragma unroll
        for (int j = 0; j < 4; j++)
#pragma unroll
            for (int e = 0; e < 4; e++) acc[i][j][e] = 0.f;

    constexpr int NCH = KTOT / KC;

    // ---- stage loader: 256 threads x 4 iters x (16B A + 16B B) ----
    auto issue_loads = [&](int c) {
        const int k0 = c * KC;
        const uint32_t dbase = sb + (uint32_t)(c & 1) * STAGE_BYTES;
#pragma unroll
        for (int i = 0; i < 4; i++) {
            int idx = tid + i * 256;                 // 0..1023
            int r = idx >> 3, s8 = idx & 7;          // row, 16B segment
            uint32_t off = (uint32_t)(r * 128 + ((s8 ^ (r & 7)) << 4));
            const void* srcA = A  + (size_t)(m0 + r) * KTOT + k0 + s8 * 8;
            asm volatile("cp.async.cg.shared.global [%0], [%1], 16;"
                         :: "r"(dbase + off), "l"(srcA));
            const void* srcB = Bw + (size_t)(n0 + r) * KTOT + k0 + s8 * 8;
            asm volatile("cp.async.cg.shared.global [%0], [%1], 16;"
                         :: "r"(dbase + 16384u + off), "l"(srcB));
        }
    };

    issue_loads(0);
    asm volatile("cp.async.commit_group;");

    for (int c = 0; c < NCH; c++) {
        if (c + 1 < NCH) issue_loads(c + 1);
        asm volatile("cp.async.commit_group;");
        asm volatile("cp.async.wait_group 1;");
        __syncthreads();

        const uint32_t sA = sb + (uint32_t)(c & 1) * STAGE_BYTES;
        const uint32_t sB = sA + 16384u;
#pragma unroll
        for (int ks = 0; ks < 4; ks++) {
            uint32_t a[4][4];
#pragma unroll
            for (int mi = 0; mi < 4; mi++) {
                int row = warp_m * 64 + mi * 16 + (lane & 15);
                int seg = ks * 2 + (lane >> 4);
                uint32_t ad = sA + (uint32_t)(row * 128 + ((seg ^ (row & 7)) << 4));
                asm volatile("ldmatrix.sync.aligned.m8n8.x4.shared.b16 {%0,%1,%2,%3}, [%4];"
                             : "=r"(a[mi][0]), "=r"(a[mi][1]), "=r"(a[mi][2]), "=r"(a[mi][3])
                             : "r"(ad));
            }
            uint32_t b[2][4];
#pragma unroll
            for (int bi = 0; bi < 2; bi++) {
                int nrow = warp_n * 32 + bi * 16 + (lane & 7) + ((lane >> 4) << 3);
                int seg = ks * 2 + ((lane >> 3) & 1);
                uint32_t ad = sB + (uint32_t)(nrow * 128 + ((seg ^ (nrow & 7)) << 4));
                asm volatile("ldmatrix.sync.aligned.m8n8.x4.shared.b16 {%0,%1,%2,%3}, [%4];"
                             : "=r"(b[bi][0]), "=r"(b[bi][1]), "=r"(b[bi][2]), "=r"(b[bi][3])
                             : "r"(ad));
            }
#pragma unroll
            for (int mi = 0; mi < 4; mi++)
#pragma unroll
                for (int ni = 0; ni < 4; ni++) {
                    uint32_t b0 = b[ni >> 1][(ni & 1) * 2];
                    uint32_t b1 = b[ni >> 1][(ni & 1) * 2 + 1];
                    asm volatile(
                        "mma.sync.aligned.m16n8k16.row.col.f32.bf16.bf16.f32 "
                        "{%0,%1,%2,%3}, {%4,%5,%6,%7}, {%8,%9}, {%0,%1,%2,%3};"
                        : "+f"(acc[mi][ni][0]), "+f"(acc[mi][ni][1]),
                          "+f"(acc[mi][ni][2]), "+f"(acc[mi][ni][3])
                        : "r"(a[mi][0]), "r"(a[mi][1]), "r"(a[mi][2]), "r"(a[mi][3]),
                          "r"(b0), "r"(b1));
                }
        }
        __syncthreads();
    }

    // ---- epilogue ----
    const int q = lane >> 2;         // row within 8
    const int tq = lane & 3;         // column pair
#pragma unroll
    for (int mi = 0; mi < 4; mi++) {
#pragma unroll
        for (int h = 0; h < 2; h++) {
            const int m = m0 + warp_m * 64 + mi * 16 + h * 8 + q;
#pragma unroll
            for (int ni = 0; ni < 4; ni++) {
                const int col = n0 + warp_n * 32 + ni * 8 + tq * 2;
                float v0 = acc[mi][ni][h * 2 + 0];
                float v1 = acc[mi][ni][h * 2 + 1];
                if (EPI == 0) {
                    __nv_bfloat16* d0 = (__nv_bfloat16*)outp + (size_t)m * K2 + col;
                    float h0 = __bfloat162float(__float2bfloat16_rn(v0));
                    float h1 = __bfloat162float(__float2bfloat16_rn(v1));
                    uint32_t uh = bf2u(h0, h1);
                    uint32_t ul = bf2u(v0 - h0, v1 - h1);
                    *(uint32_t*)(d0)       = uh;
                    *(uint32_t*)(d0 + 256) = uh;
                    *(uint32_t*)(d0 + 512) = ul;
                } else if (EPI == 1) {
                    __nv_bfloat16* d0 = (__nv_bfloat16*)outp + (size_t)m * K1 + col;
                    float z0 = v0 + __ldg(bias + col);
                    float z1 = v1 + __ldg(bias + col + 1);
                    float y0 = sinf(z0), y1 = sinf(z1);
                    float h0 = __bfloat162float(__float2bfloat16_rn(y0));
                    float h1 = __bfloat162float(__float2bfloat16_rn(y1));
                    float yy0 = y0 * y0, yy1 = y1 * y1;
                    uint32_t uh = bf2u(h0, h1);
                    *(uint32_t*)(d0)        = uh;
                    *(uint32_t*)(d0 + 256)  = uh;
                    *(uint32_t*)(d0 + 512)  = bf2u(y0 - h0, y1 - h1);
                    *(uint32_t*)(d0 + 768)  = bf2u(y0 * yy0, y1 * yy1);
                    *(uint32_t*)(d0 + 1024) = bf2u(y0 * yy0 * yy0, y1 * yy1 * yy1);
                } else {
                    float* O = (float*)outp + (size_t)m * HID + col;
                    *reinterpret_cast<float2*>(O) = make_float2(v0, v1);
                }
            }
        }
    }
}

// coords passthrough (tuple element #2)
__global__ void copy_kernel(const float* __restrict__ src, float* __restrict__ dst, int n) {
    int i = blockIdx.x * blockDim.x + threadIdx.x;
    if (i < n) dst[i] = src[i];
}

extern "C" void kernel_launch(void* const* d_in, const int* in_sizes, int n_in,
                              void* d_out, int out_size) {
    const float* coords = (const float*)d_in[0];  // (4096, 6)
    const float* B      = (const float*)d_in[1];  // (3, 128)
    const float* w0     = (const float*)d_in[2];  // (256, 256)
    const float* ws     = (const float*)d_in[3];  // (3, 256, 256)
    const float* w_last = (const float*)d_in[4];  // (256, 256)
    const float* w1     = (const float*)d_in[5];  // (4, 256, 256)
    const float* b1     = (const float*)d_in[6];  // (4, 256)
    float* out = (float*)d_out;

    __nv_bfloat16 *Xexp, *Sexp, *Wsin, *Wmm;
    cudaGetSymbolAddress((void**)&Xexp, g_Xexp);
    cudaGetSymbolAddress((void**)&Sexp, g_Sexp);
    cudaGetSymbolAddress((void**)&Wsin, g_Wsin);
    cudaGetSymbolAddress((void**)&Wmm,  g_Wmm);

    cudaFuncSetAttribute(gemm_kernel<K1, 0>, cudaFuncAttributeMaxDynamicSharedMemorySize, SMEM_TOTAL);
    cudaFuncSetAttribute(gemm_kernel<K2, 1>, cudaFuncAttributeMaxDynamicSharedMemorySize, SMEM_TOTAL);
    cudaFuncSetAttribute(gemm_kernel<K1, 2>, cudaFuncAttributeMaxDynamicSharedMemorySize, SMEM_TOTAL);

    // weight expansion (cheap, deterministic, every launch)
    prep_sin_kernel<<<dim3(256, 5), 256>>>(w0, ws, w_last, Wsin);
    prep_mm_kernel<<<dim3(256, 4), 256>>>(w1, Wmm);
    // Fourier features, directly expanded
    fourier_kernel<<<MROWS, 128>>>(coords, B, Xexp);

    const dim3 grid(MROWS / TILE_M, HID / TILE_N);  // (64, 2)
    for (int i = 0; i < 4; i++) {
        gemm_kernel<K1, 0><<<grid, 256, SMEM_TOTAL>>>(Xexp, Wsin + (size_t)i * HID * K1, nullptr, Sexp);
        gemm_kernel<K2, 1><<<grid, 256, SMEM_TOTAL>>>(Sexp, Wmm + (size_t)i * HID * K2, b1 + i * 256, Xexp);
    }
    gemm_kernel<K1, 2><<<grid, 256, SMEM_TOTAL>>>(Xexp, Wsin + (size_t)4 * HID * K1, nullptr, out);
    copy_kernel<<<(NCOORD + 255) / 256, 256>>>(coords, out + (size_t)MROWS * HID, NCOORD);
}

// round 5
// speedup vs baseline: 5.6952x; 1.0420x over previous
#include <cuda_runtime.h>
#include <cuda_bf16.h>
#include <cstdint>

// ---------------- problem constants ----------------
#define MROWS 8192          // 2*N rows
#define HID   256
#define K1    1280          // sin_layer expanded K: [x_hi, x_hi, x_lo, x^3, x^5]
#define K2    768           // matmul expanded K:    [s_hi, s_hi, s_lo]
#define NCOORD (4096 * 6)

#define TILE_M 64
#define TILE_N 128
#define KC     64                 // K chunk: 64 bf16 = 128B rows
#define STAGE_A  8192              // 64 rows * 128B
#define STAGE_BYTES 24576          // A 8KB + B 16KB
#define NSTAGE 3
#define SMEM_TOTAL (NSTAGE * STAGE_BYTES)   // 73728

// ---------------- device scratch (allocation-free) ----------------
__device__ __align__(256) __nv_bfloat16 g_Xexp[(size_t)MROWS * K1];
__device__ __align__(256) __nv_bfloat16 g_Sexp[(size_t)MROWS * K2];
__device__ __align__(256) __nv_bfloat16 g_Wsin[(size_t)5 * HID * K1];
__device__ __align__(256) __nv_bfloat16 g_Wmm [(size_t)4 * HID * K2];

// ---------------- helpers ----------------
__device__ __forceinline__ uint32_t smem_u32(const void* p) {
    uint32_t a;
    asm("{ .reg .u64 t; cvta.to.shared.u64 t, %1; cvt.u32.u64 %0, t; }" : "=r"(a) : "l"(p));
    return a;
}
__device__ __forceinline__ uint32_t bf2u(float a, float b) {
    __nv_bfloat162 t = __floats2bfloat162_rn(a, b);
    return *reinterpret_cast<uint32_t*>(&t);
}

// ---------------- weight expansion kernels ----------------
// sin weights: slots [w_hi, w_lo, w_hi, -w^3/6, w^5/120]
__global__ void prep_sin_kernel(const float* __restrict__ w0, const float* __restrict__ ws,
                                const float* __restrict__ w_last, __nv_bfloat16* __restrict__ out) {
    int l = blockIdx.y;
    int idx = blockIdx.x * 256 + threadIdx.x;       // 0..65535
    const float* src = (l == 0) ? w0 : (l <= 3 ? ws + (l - 1) * 65536 : w_last);
    float w = src[idx];
    int h = idx >> 8, k = idx & 255;
    __nv_bfloat16* o = out + (size_t)l * HID * K1 + (size_t)h * K1 + k;
    float hi = __bfloat162float(__float2bfloat16_rn(w));
    float lo = w - hi;
    float ww = w * w;
    o[0]    = __float2bfloat16_rn(hi);
    o[256]  = __float2bfloat16_rn(lo);
    o[512]  = __float2bfloat16_rn(hi);
    o[768]  = __float2bfloat16_rn(-w * ww * (1.0f / 6.0f));
    o[1024] = __float2bfloat16_rn(w * ww * ww * (1.0f / 120.0f));
}
// matmul weights: slots [w_hi, w_lo, w_hi]
__global__ void prep_mm_kernel(const float* __restrict__ w1, __nv_bfloat16* __restrict__ out) {
    int l = blockIdx.y;
    int idx = blockIdx.x * 256 + threadIdx.x;
    float w = w1[(size_t)l * 65536 + idx];
    int h = idx >> 8, k = idx & 255;
    __nv_bfloat16* o = out + (size_t)l * HID * K2 + (size_t)h * K2 + k;
    float hi = __bfloat162float(__float2bfloat16_rn(w));
    float lo = w - hi;
    o[0]   = __float2bfloat16_rn(hi);
    o[256] = __float2bfloat16_rn(lo);
    o[512] = __float2bfloat16_rn(hi);
}

// ---------------- Fourier features -> expanded activations ----------------
__device__ __forceinline__ void write5(__nv_bfloat16* r, int j, float v) {
    float hi = __bfloat162float(__float2bfloat16_rn(v));
    float lo = v - hi;
    float vv = v * v;
    r[j]        = __float2bfloat16_rn(hi);
    r[256 + j]  = __float2bfloat16_rn(hi);
    r[512 + j]  = __float2bfloat16_rn(lo);
    r[768 + j]  = __float2bfloat16_rn(v * vv);
    r[1024 + j] = __float2bfloat16_rn(v * vv * vv);
}
__global__ void fourier_kernel(const float* __restrict__ coords, const float* __restrict__ B,
                               __nv_bfloat16* __restrict__ X) {
    int m = blockIdx.x;       // 0..8191
    int f = threadIdx.x;      // 0..127
    float x0, x1, x2;
    if (m < 4096) {
        const float* c = coords + m * 6;
        x0 = c[0]; x1 = c[1]; x2 = c[2];
    } else {
        const float* c = coords + (m - 4096) * 6;
        x0 = c[3]; x1 = c[4]; x2 = c[5];
    }
    float p = x0 * __ldg(&B[f]) + x1 * __ldg(&B[128 + f]) + x2 * __ldg(&B[256 + f]);
    p *= 6.283185307179586f;
    __nv_bfloat16* r = X + (size_t)m * K1;
    write5(r, f, sinf(p));
    write5(r, 128 + f, cosf(p));
}

// ---------------- HMMA GEMM with fused epilogue ----------------
// D[m,n] = sum_k A[m,k]*B[n,k]  (both K-major), fp32 accum.
// CTA tile 64x128, 8 warps, warp tile 32x32, 3-stage cp.async pipeline.
// EPI 0: 3-slot split of D -> Sexp (K2 layout)
// EPI 1: y = sin(D + bias[n]) -> 5-slot expansion -> Xexp (K1 layout)
// EPI 2: fp32 D -> out
template <int KTOT, int EPI>
__global__ __launch_bounds__(256, 2)
void gemm_kernel(const __nv_bfloat16* __restrict__ A, const __nv_bfloat16* __restrict__ Bw,
                 const float* __restrict__ bias, void* __restrict__ outp) {
    extern __shared__ char smem[];
    const uint32_t sb = smem_u32(smem);
    const int tid = threadIdx.x;
    const int lane = tid & 31;
    const int wid = tid >> 5;
    const int warp_m = wid & 1;     // 0..1 : 32-row slab
    const int warp_n = wid >> 1;    // 0..3 : 32-col slab
    const int m0 = blockIdx.x * TILE_M;
    const int n0 = blockIdx.y * TILE_N;

    float acc[2][4][4];
#pragma unroll
    for (int i = 0; i < 2; i++)
#pragma unroll
        for (int j = 0; j < 4; j++)
#pragma unroll
            for (int e = 0; e < 4; e++) acc[i][j][e] = 0.f;

    constexpr int NCH = KTOT / KC;

    // ---- stage loader ----
    auto issue_loads = [&](int c) {
        const int k0 = c * KC;
        const uint32_t dbase = sb + (uint32_t)(c % NSTAGE) * STAGE_BYTES;
        // A tile: 64 rows x 8 segs = 512 requests (2 per thread)
#pragma unroll
        for (int i = 0; i < 2; i++) {
            int idx = tid + i * 256;
            int r = idx >> 3, s8 = idx & 7;
            uint32_t off = (uint32_t)(r * 128 + ((s8 ^ (r & 7)) << 4));
            const void* srcA = A + (size_t)(m0 + r) * KTOT + k0 + s8 * 8;
            asm volatile("cp.async.cg.shared.global [%0], [%1], 16;"
                         :: "r"(dbase + off), "l"(srcA));
        }
        // B tile: 128 rows x 8 segs = 1024 requests (4 per thread)
#pragma unroll
        for (int i = 0; i < 4; i++) {
            int idx = tid + i * 256;
            int r = idx >> 3, s8 = idx & 7;
            uint32_t off = (uint32_t)(r * 128 + ((s8 ^ (r & 7)) << 4));
            const void* srcB = Bw + (size_t)(n0 + r) * KTOT + k0 + s8 * 8;
            asm volatile("cp.async.cg.shared.global [%0], [%1], 16;"
                         :: "r"(dbase + STAGE_A + off), "l"(srcB));
        }
    };

    issue_loads(0);
    asm volatile("cp.async.commit_group;");
    issue_loads(1);
    asm volatile("cp.async.commit_group;");

    for (int c = 0; c < NCH; c++) {
        asm volatile("cp.async.wait_group 1;");   // stage c complete (per-thread)
        __syncthreads();                          // stage c visible; compute c-1 done by all
        if (c + 2 < NCH) issue_loads(c + 2);      // overwrite stage (c+2)%3 (consumed at c-1)
        asm volatile("cp.async.commit_group;");   // commit (possibly empty) keeps count regular

        const uint32_t sA = sb + (uint32_t)(c % NSTAGE) * STAGE_BYTES;
        const uint32_t sB = sA + STAGE_A;
#pragma unroll
        for (int ks = 0; ks < 4; ks++) {
            uint32_t a[2][4];
#pragma unroll
            for (int mi = 0; mi < 2; mi++) {
                int row = warp_m * 32 + mi * 16 + (lane & 15);
                int seg = ks * 2 + (lane >> 4);
                uint32_t ad = sA + (uint32_t)(row * 128 + ((seg ^ (row & 7)) << 4));
                asm volatile("ldmatrix.sync.aligned.m8n8.x4.shared.b16 {%0,%1,%2,%3}, [%4];"
                             : "=r"(a[mi][0]), "=r"(a[mi][1]), "=r"(a[mi][2]), "=r"(a[mi][3])
                             : "r"(ad));
            }
            uint32_t b[2][4];
#pragma unroll
            for (int bi = 0; bi < 2; bi++) {
                int nrow = warp_n * 32 + bi * 16 + (lane & 7) + ((lane >> 4) << 3);
                int seg = ks * 2 + ((lane >> 3) & 1);
                uint32_t ad = sB + (uint32_t)(nrow * 128 + ((seg ^ (nrow & 7)) << 4));
                asm volatile("ldmatrix.sync.aligned.m8n8.x4.shared.b16 {%0,%1,%2,%3}, [%4];"
                             : "=r"(b[bi][0]), "=r"(b[bi][1]), "=r"(b[bi][2]), "=r"(b[bi][3])
                             : "r"(ad));
            }
#pragma unroll
            for (int mi = 0; mi < 2; mi++)
#pragma unroll
                for (int ni = 0; ni < 4; ni++) {
                    uint32_t b0 = b[ni >> 1][(ni & 1) * 2];
                    uint32_t b1 = b[ni >> 1][(ni & 1) * 2 + 1];
                    asm volatile(
                        "mma.sync.aligned.m16n8k16.row.col.f32.bf16.bf16.f32 "
                        "{%0,%1,%2,%3}, {%4,%5,%6,%7}, {%8,%9}, {%0,%1,%2,%3};"
                        : "+f"(acc[mi][ni][0]), "+f"(acc[mi][ni][1]),
                          "+f"(acc[mi][ni][2]), "+f"(acc[mi][ni][3])
                        : "r"(a[mi][0]), "r"(a[mi][1]), "r"(a[mi][2]), "r"(a[mi][3]),
                          "r"(b0), "r"(b1));
                }
        }
    }

    // ---- epilogue ----
    const int q = lane >> 2;         // row within 8
    const int tq = lane & 3;         // column pair
#pragma unroll
    for (int mi = 0; mi < 2; mi++) {
#pragma unroll
        for (int h = 0; h < 2; h++) {
            const int m = m0 + warp_m * 32 + mi * 16 + h * 8 + q;
#pragma unroll
            for (int ni = 0; ni < 4; ni++) {
                const int col = n0 + warp_n * 32 + ni * 8 + tq * 2;
                float v0 = acc[mi][ni][h * 2 + 0];
                float v1 = acc[mi][ni][h * 2 + 1];
                if (EPI == 0) {
                    __nv_bfloat16* d0 = (__nv_bfloat16*)outp + (size_t)m * K2 + col;
                    float h0 = __bfloat162float(__float2bfloat16_rn(v0));
                    float h1 = __bfloat162float(__float2bfloat16_rn(v1));
                    uint32_t uh = bf2u(h0, h1);
                    uint32_t ul = bf2u(v0 - h0, v1 - h1);
                    *(uint32_t*)(d0)       = uh;
                    *(uint32_t*)(d0 + 256) = uh;
                    *(uint32_t*)(d0 + 512) = ul;
                } else if (EPI == 1) {
                    __nv_bfloat16* d0 = (__nv_bfloat16*)outp + (size_t)m * K1 + col;
                    float z0 = v0 + __ldg(bias + col);
                    float z1 = v1 + __ldg(bias + col + 1);
                    float y0 = sinf(z0), y1 = sinf(z1);
                    float h0 = __bfloat162float(__float2bfloat16_rn(y0));
                    float h1 = __bfloat162float(__float2bfloat16_rn(y1));
                    float yy0 = y0 * y0, yy1 = y1 * y1;
                    uint32_t uh = bf2u(h0, h1);
                    *(uint32_t*)(d0)        = uh;
                    *(uint32_t*)(d0 + 256)  = uh;
                    *(uint32_t*)(d0 + 512)  = bf2u(y0 - h0, y1 - h1);
                    *(uint32_t*)(d0 + 768)  = bf2u(y0 * yy0, y1 * yy1);
                    *(uint32_t*)(d0 + 1024) = bf2u(y0 * yy0 * yy0, y1 * yy1 * yy1);
                } else {
                    float* O = (float*)outp + (size_t)m * HID + col;
                    *reinterpret_cast<float2*>(O) = make_float2(v0, v1);
                }
            }
        }
    }
}

// coords passthrough (tuple element #2)
__global__ void copy_kernel(const float* __restrict__ src, float* __restrict__ dst, int n) {
    int i = blockIdx.x * blockDim.x + threadIdx.x;
    if (i < n) dst[i] = src[i];
}

extern "C" void kernel_launch(void* const* d_in, const int* in_sizes, int n_in,
                              void* d_out, int out_size) {
    const float* coords = (const float*)d_in[0];  // (4096, 6)
    const float* B      = (const float*)d_in[1];  // (3, 128)
    const float* w0     = (const float*)d_in[2];  // (256, 256)
    const float* ws     = (const float*)d_in[3];  // (3, 256, 256)
    const float* w_last = (const float*)d_in[4];  // (256, 256)
    const float* w1     = (const float*)d_in[5];  // (4, 256, 256)
    const float* b1     = (const float*)d_in[6];  // (4, 256)
    float* out = (float*)d_out;

    __nv_bfloat16 *Xexp, *Sexp, *Wsin, *Wmm;
    cudaGetSymbolAddress((void**)&Xexp, g_Xexp);
    cudaGetSymbolAddress((void**)&Sexp, g_Sexp);
    cudaGetSymbolAddress((void**)&Wsin, g_Wsin);
    cudaGetSymbolAddress((void**)&Wmm,  g_Wmm);

    cudaFuncSetAttribute(gemm_kernel<K1, 0>, cudaFuncAttributeMaxDynamicSharedMemorySize, SMEM_TOTAL);
    cudaFuncSetAttribute(gemm_kernel<K2, 1>, cudaFuncAttributeMaxDynamicSharedMemorySize, SMEM_TOTAL);
    cudaFuncSetAttribute(gemm_kernel<K1, 2>, cudaFuncAttributeMaxDynamicSharedMemorySize, SMEM_TOTAL);

    // weight expansion (cheap, deterministic, every launch)
    prep_sin_kernel<<<dim3(256, 5), 256>>>(w0, ws, w_last, Wsin);
    prep_mm_kernel<<<dim3(256, 4), 256>>>(w1, Wmm);
    // Fourier features, directly expanded
    fourier_kernel<<<MROWS, 128>>>(coords, B, Xexp);

    const dim3 grid(MROWS / TILE_M, HID / TILE_N);  // (128, 2) = 256 CTAs
    for (int i = 0; i < 4; i++) {
        gemm_kernel<K1, 0><<<grid, 256, SMEM_TOTAL>>>(Xexp, Wsin + (size_t)i * HID * K1, nullptr, Sexp);
        gemm_kernel<K2, 1><<<grid, 256, SMEM_TOTAL>>>(Sexp, Wmm + (size_t)i * HID * K2, b1 + i * 256, Xexp);
    }
    gemm_kernel<K1, 2><<<grid, 256, SMEM_TOTAL>>>(Xexp, Wsin + (size_t)4 * HID * K1, nullptr, out);
    copy_kernel<<<(NCOORD + 255) / 256, 256>>>(coords, out + (size_t)MROWS * HID, NCOORD);
}

// round 7
// speedup vs baseline: 6.3633x; 1.1173x over previous
#include <cuda_runtime.h>
#include <cuda_bf16.h>
#include <cstdint>

// ---------------- problem constants ----------------
#define MROWS 8192          // 2*N rows
#define HID   256
#define K1    1024          // sin_layer expanded K: [x_hi, x_hi, x_lo, x^3]
#define K2    768           // matmul expanded K:    [s_hi, s_hi, s_lo]
#define NCOORD (4096 * 6)

#define TILE_M 64
#define TILE_N 128
#define KC     64                  // K chunk: 64 bf16 = 128B rows
#define STAGE_A  8192               // 64 rows * 128B
#define STAGE_BYTES 24576           // A 8KB + B 16KB
#define NSTAGE 4
#define SMEM_TOTAL (NSTAGE * STAGE_BYTES)   // 98304

// ---------------- device scratch (allocation-free) ----------------
__device__ __align__(256) __nv_bfloat16 g_Xexp[(size_t)MROWS * K1];
__device__ __align__(256) __nv_bfloat16 g_Sexp[(size_t)MROWS * K2];
__device__ __align__(256) __nv_bfloat16 g_Wsin[(size_t)5 * HID * K1];
__device__ __align__(256) __nv_bfloat16 g_Wmm [(size_t)4 * HID * K2];

// ---------------- helpers ----------------
__device__ __forceinline__ uint32_t smem_u32(const void* p) {
    uint32_t a;
    asm("{ .reg .u64 t; cvta.to.shared.u64 t, %1; cvt.u32.u64 %0, t; }" : "=r"(a) : "l"(p));
    return a;
}
__device__ __forceinline__ uint32_t bf2u(float a, float b) {
    __nv_bfloat162 t = __floats2bfloat162_rn(a, b);
    return *reinterpret_cast<uint32_t*>(&t);
}

// ---------------- weight expansion kernels ----------------
// sin weights: slots [w_hi, w_lo, w_hi, -w^3/6]
__global__ void prep_sin_kernel(const float* __restrict__ w0, const float* __restrict__ ws,
                                const float* __restrict__ w_last, __nv_bfloat16* __restrict__ out) {
    int l = blockIdx.y;
    int idx = blockIdx.x * 256 + threadIdx.x;       // 0..65535
    const float* src = (l == 0) ? w0 : (l <= 3 ? ws + (l - 1) * 65536 : w_last);
    float w = src[idx];
    int h = idx >> 8, k = idx & 255;
    __nv_bfloat16* o = out + (size_t)l * HID * K1 + (size_t)h * K1 + k;
    float hi = __bfloat162float(__float2bfloat16_rn(w));
    float lo = w - hi;
    float ww = w * w;
    o[0]    = __float2bfloat16_rn(hi);
    o[256]  = __float2bfloat16_rn(lo);
    o[512]  = __float2bfloat16_rn(hi);
    o[768]  = __float2bfloat16_rn(-w * ww * (1.0f / 6.0f));
}
// matmul weights: slots [w_hi, w_lo, w_hi]
__global__ void prep_mm_kernel(const float* __restrict__ w1, __nv_bfloat16* __restrict__ out) {
    int l = blockIdx.y;
    int idx = blockIdx.x * 256 + threadIdx.x;
    float w = w1[(size_t)l * 65536 + idx];
    int h = idx >> 8, k = idx & 255;
    __nv_bfloat16* o = out + (size_t)l * HID * K2 + (size_t)h * K2 + k;
    float hi = __bfloat162float(__float2bfloat16_rn(w));
    float lo = w - hi;
    o[0]   = __float2bfloat16_rn(hi);
    o[256] = __float2bfloat16_rn(lo);
    o[512] = __float2bfloat16_rn(hi);
}

// ---------------- Fourier features -> expanded activations ----------------
__device__ __forceinline__ void write4(__nv_bfloat16* r, int j, float v) {
    float hi = __bfloat162float(__float2bfloat16_rn(v));
    float lo = v - hi;
    r[j]       = __float2bfloat16_rn(hi);
    r[256 + j] = __float2bfloat16_rn(hi);
    r[512 + j] = __float2bfloat16_rn(lo);
    r[768 + j] = __float2bfloat16_rn(v * v * v);
}
__global__ void fourier_kernel(const float* __restrict__ coords, const float* __restrict__ B,
                               __nv_bfloat16* __restrict__ X) {
    int m = blockIdx.x;       // 0..8191
    int f = threadIdx.x;      // 0..127
    float x0, x1, x2;
    if (m < 4096) {
        const float* c = coords + m * 6;
        x0 = c[0]; x1 = c[1]; x2 = c[2];
    } else {
        const float* c = coords + (m - 4096) * 6;
        x0 = c[3]; x1 = c[4]; x2 = c[5];
    }
    float p = x0 * __ldg(&B[f]) + x1 * __ldg(&B[128 + f]) + x2 * __ldg(&B[256 + f]);
    p *= 6.283185307179586f;
    __nv_bfloat16* r = X + (size_t)m * K1;
    write4(r, f, sinf(p));
    write4(r, 128 + f, cosf(p));
}

// ---------------- HMMA GEMM with fused epilogue ----------------
// D[m,n] = sum_k A[m,k]*B[n,k]  (both K-major), fp32 accum.
// CTA tile 64x128, 8 warps (warp tile 32x32), 4-stage cp.async, depth-2
// prefetch, software-pipelined ldmatrix fragments.
// EPI 0: 3-slot split of D -> Sexp (K2 layout)
// EPI 1: y = sin(D + bias[n]) -> 4-slot expansion -> Xexp (K1 layout)
// EPI 2: fp32 D -> out
template <int KTOT, int EPI>
__global__ __launch_bounds__(256, 2)
void gemm_kernel(const __nv_bfloat16* __restrict__ A, const __nv_bfloat16* __restrict__ Bw,
                 const float* __restrict__ bias, void* __restrict__ outp) {
    extern __shared__ char smem[];
    const uint32_t sb = smem_u32(smem);
    const int tid = threadIdx.x;
    const int lane = tid & 31;
    const int wid = tid >> 5;
    const int warp_m = wid & 1;     // 0..1 : 32-row slab
    const int warp_n = wid >> 1;    // 0..3 : 32-col slab
    const int m0 = blockIdx.x * TILE_M;
    const int n0 = blockIdx.y * TILE_N;

    float acc[2][4][4];
#pragma unroll
    for (int i = 0; i < 2; i++)
#pragma unroll
        for (int j = 0; j < 4; j++)
#pragma unroll
            for (int e = 0; e < 4; e++) acc[i][j][e] = 0.f;

    constexpr int NCH = KTOT / KC;

    // ---- stage loader ----
    auto issue_loads = [&](int c) {
        const int k0 = c * KC;
        const uint32_t dbase = sb + (uint32_t)(c % NSTAGE) * STAGE_BYTES;
#pragma unroll
        for (int i = 0; i < 2; i++) {              // A: 64 rows x 8 segs
            int idx = tid + i * 256;
            int r = idx >> 3, s8 = idx & 7;
            uint32_t off = (uint32_t)(r * 128 + ((s8 ^ (r & 7)) << 4));
            const void* srcA = A + (size_t)(m0 + r) * KTOT + k0 + s8 * 8;
            asm volatile("cp.async.cg.shared.global [%0], [%1], 16;"
                         :: "r"(dbase + off), "l"(srcA));
        }
#pragma unroll
        for (int i = 0; i < 4; i++) {              // B: 128 rows x 8 segs
            int idx = tid + i * 256;
            int r = idx >> 3, s8 = idx & 7;
            uint32_t off = (uint32_t)(r * 128 + ((s8 ^ (r & 7)) << 4));
            const void* srcB = Bw + (size_t)(n0 + r) * KTOT + k0 + s8 * 8;
            asm volatile("cp.async.cg.shared.global [%0], [%1], 16;"
                         :: "r"(dbase + STAGE_A + off), "l"(srcB));
        }
    };

    // fragment loader for one ks step (K=16 slice)
    auto load_frags = [&](uint32_t sA, uint32_t sB, int ks,
                          uint32_t (*af)[4], uint32_t (*bfr)[4]) {
#pragma unroll
        for (int mi = 0; mi < 2; mi++) {
            int row = warp_m * 32 + mi * 16 + (lane & 15);
            int seg = ks * 2 + (lane >> 4);
            uint32_t ad = sA + (uint32_t)(row * 128 + ((seg ^ (row & 7)) << 4));
            asm volatile("ldmatrix.sync.aligned.m8n8.x4.shared.b16 {%0,%1,%2,%3}, [%4];"
                         : "=r"(af[mi][0]), "=r"(af[mi][1]), "=r"(af[mi][2]), "=r"(af[mi][3])
                         : "r"(ad));
        }
#pragma unroll
        for (int bi = 0; bi < 2; bi++) {
            int nrow = warp_n * 32 + bi * 16 + (lane & 7) + ((lane >> 4) << 3);
            int seg = ks * 2 + ((lane >> 3) & 1);
            uint32_t ad = sB + (uint32_t)(nrow * 128 + ((seg ^ (nrow & 7)) << 4));
            asm volatile("ldmatrix.sync.aligned.m8n8.x4.shared.b16 {%0,%1,%2,%3}, [%4];"
                         : "=r"(bfr[bi][0]), "=r"(bfr[bi][1]), "=r"(bfr[bi][2]), "=r"(bfr[bi][3])
                         : "r"(ad));
        }
    };

    // prologue: 3 chunks in flight
    issue_loads(0); asm volatile("cp.async.commit_group;");
    issue_loads(1); asm volatile("cp.async.commit_group;");
    issue_loads(2); asm volatile("cp.async.commit_group;");

    for (int c = 0; c < NCH; c++) {
        asm volatile("cp.async.wait_group 2;");   // stage c complete
        __syncthreads();                          // visible to all; compute c-1 done
        if (c + 3 < NCH) issue_loads(c + 3);      // buf (c+3)%4, consumed at c-1
        asm volatile("cp.async.commit_group;");

        const uint32_t sA = sb + (uint32_t)(c % NSTAGE) * STAGE_BYTES;
        const uint32_t sB = sA + STAGE_A;

        uint32_t af[2][2][4], bf[2][2][4];        // double-buffered fragments
        load_frags(sA, sB, 0, af[0], bf[0]);
#pragma unroll
        for (int ks = 0; ks < 4; ks++) {
            if (ks < 3) load_frags(sA, sB, ks + 1, af[(ks + 1) & 1], bf[(ks + 1) & 1]);
            uint32_t (*a)[4] = af[ks & 1];
            uint32_t (*b)[4] = bf[ks & 1];
#pragma unroll
            for (int mi = 0; mi < 2; mi++)
#pragma unroll
                for (int ni = 0; ni < 4; ni++) {
                    uint32_t b0 = b[ni >> 1][(ni & 1) * 2];
                    uint32_t b1 = b[ni >> 1][(ni & 1) * 2 + 1];
                    asm volatile(
                        "mma.sync.aligned.m16n8k16.row.col.f32.bf16.bf16.f32 "
                        "{%0,%1,%2,%3}, {%4,%5,%6,%7}, {%8,%9}, {%0,%1,%2,%3};"
                        : "+f"(acc[mi][ni][0]), "+f"(acc[mi][ni][1]),
                          "+f"(acc[mi][ni][2]), "+f"(acc[mi][ni][3])
                        : "r"(a[mi][0]), "r"(a[mi][1]), "r"(a[mi][2]), "r"(a[mi][3]),
                          "r"(b0), "r"(b1));
                }
        }
    }

    // ---- epilogue ----
    const int q = lane >> 2;         // row within 8
    const int tq = lane & 3;         // column pair
#pragma unroll
    for (int mi = 0; mi < 2; mi++) {
#pragma unroll
        for (int h = 0; h < 2; h++) {
            const int m = m0 + warp_m * 32 + mi * 16 + h * 8 + q;
#pragma unroll
            for (int ni = 0; ni < 4; ni++) {
                const int col = n0 + warp_n * 32 + ni * 8 + tq * 2;
                float v0 = acc[mi][ni][h * 2 + 0];
                float v1 = acc[mi][ni][h * 2 + 1];
                if (EPI == 0) {
                    __nv_bfloat16* d0 = (__nv_bfloat16*)outp + (size_t)m * K2 + col;
                    float h0 = __bfloat162float(__float2bfloat16_rn(v0));
                    float h1 = __bfloat162float(__float2bfloat16_rn(v1));
                    uint32_t uh = bf2u(h0, h1);
                    uint32_t ul = bf2u(v0 - h0, v1 - h1);
                    *(uint32_t*)(d0)       = uh;
                    *(uint32_t*)(d0 + 256) = uh;
                    *(uint32_t*)(d0 + 512) = ul;
                } else if (EPI == 1) {
                    __nv_bfloat16* d0 = (__nv_bfloat16*)outp + (size_t)m * K1 + col;
                    float z0 = v0 + __ldg(bias + col);
                    float z1 = v1 + __ldg(bias + col + 1);
                    float y0 = sinf(z0), y1 = sinf(z1);
                    float h0 = __bfloat162float(__float2bfloat16_rn(y0));
                    float h1 = __bfloat162float(__float2bfloat16_rn(y1));
                    uint32_t uh = bf2u(h0, h1);
                    *(uint32_t*)(d0)       = uh;
                    *(uint32_t*)(d0 + 256) = uh;
                    *(uint32_t*)(d0 + 512) = bf2u(y0 - h0, y1 - h1);
                    *(uint32_t*)(d0 + 768) = bf2u(y0 * y0 * y0, y1 * y1 * y1);
                } else {
                    float* O = (float*)outp + (size_t)m * HID + col;
                    *reinterpret_cast<float2*>(O) = make_float2(v0, v1);
                }
            }
        }
    }
}

// coords passthrough (tuple element #2)
__global__ void copy_kernel(const float* __restrict__ src, float* __restrict__ dst, int n) {
    int i = blockIdx.x * blockDim.x + threadIdx.x;
    if (i < n) dst[i] = src[i];
}

extern "C" void kernel_launch(void* const* d_in, const int* in_sizes, int n_in,
                              void* d_out, int out_size) {
    const float* coords = (const float*)d_in[0];  // (4096, 6)
    const float* B      = (const float*)d_in[1];  // (3, 128)
    const float* w0     = (const float*)d_in[2];  // (256, 256)
    const float* ws     = (const float*)d_in[3];  // (3, 256, 256)
    const float* w_last = (const float*)d_in[4];  // (256, 256)
    const float* w1     = (const float*)d_in[5];  // (4, 256, 256)
    const float* b1     = (const float*)d_in[6];  // (4, 256)
    float* out = (float*)d_out;

    __nv_bfloat16 *Xexp, *Sexp, *Wsin, *Wmm;
    cudaGetSymbolAddress((void**)&Xexp, g_Xexp);
    cudaGetSymbolAddress((void**)&Sexp, g_Sexp);
    cudaGetSymbolAddress((void**)&Wsin, g_Wsin);
    cudaGetSymbolAddress((void**)&Wmm,  g_Wmm);

    cudaFuncSetAttribute(gemm_kernel<K1, 0>, cudaFuncAttributeMaxDynamicSharedMemorySize, SMEM_TOTAL);
    cudaFuncSetAttribute(gemm_kernel<K2, 1>, cudaFuncAttributeMaxDynamicSharedMemorySize, SMEM_TOTAL);
    cudaFuncSetAttribute(gemm_kernel<K1, 2>, cudaFuncAttributeMaxDynamicSharedMemorySize, SMEM_TOTAL);

    // weight expansion (cheap, deterministic, every launch)
    prep_sin_kernel<<<dim3(256, 5), 256>>>(w0, ws, w_last, Wsin);
    prep_mm_kernel<<<dim3(256, 4), 256>>>(w1, Wmm);
    // Fourier features, directly expanded
    fourier_kernel<<<MROWS, 128>>>(coords, B, Xexp);

    const dim3 grid(MROWS / TILE_M, HID / TILE_N);  // (128, 2) = 256 CTAs
    for (int i = 0; i < 4; i++) {
        gemm_kernel<K1, 0><<<grid, 256, SMEM_TOTAL>>>(Xexp, Wsin + (size_t)i * HID * K1, nullptr, Sexp);
        gemm_kernel<K2, 1><<<grid, 256, SMEM_TOTAL>>>(Sexp, Wmm + (size_t)i * HID * K2, b1 + i * 256, Xexp);
    }
    gemm_kernel<K1, 2><<<grid, 256, SMEM_TOTAL>>>(Xexp, Wsin + (size_t)4 * HID * K1, nullptr, out);
    copy_kernel<<<(NCOORD + 255) / 256, 256>>>(coords, out + (size_t)MROWS * HID, NCOORD);
}

// round 9
// speedup vs baseline: 9.0044x; 1.4150x over previous
#include <cuda_runtime.h>
#include <cuda_bf16.h>
#include <cstdint>

// ---------------- problem constants ----------------
#define MROWS 8192          // 2*N rows
#define HID   256
#define K1    1024          // expanded K: [x_hi, x_hi, x_lo, x^3]
#define KW    768           // hi/lo split K for C1 prep
#define NCOORD (4096 * 6)

#define TILE_M 64
#define TILE_N 128
#define KC     64                  // K chunk: 64 bf16 = 128B rows
#define STAGE_A  8192               // 64 rows * 128B
#define STAGE_BYTES 24576           // A 8KB + B 16KB
#define NSTAGE 4
#define SMEM_TOTAL (NSTAGE * STAGE_BYTES)   // 98304

// ---------------- device scratch (allocation-free) ----------------
__device__ __align__(256) __nv_bfloat16 g_XA[(size_t)MROWS * K1];   // ping
__device__ __align__(256) __nv_bfloat16 g_XB[(size_t)MROWS * K1];   // pong
__device__ __align__(256) __nv_bfloat16 g_Wexp[(size_t)5 * HID * K1]; // merged weights l=0..3 + w_last l=4
__device__ __align__(256) __nv_bfloat16 g_A1[(size_t)4 * HID * KW];   // W1 split   [hi,hi,lo]
__device__ __align__(256) __nv_bfloat16 g_A3[(size_t)4 * HID * HID];  // W1 plain
__device__ __align__(256) __nv_bfloat16 g_BT[(size_t)4 * HID * KW];   // WsinT split [hi,lo,hi]
__device__ __align__(256) __nv_bfloat16 g_BT3[(size_t)4 * HID * HID]; // (WsinT)^3/6

// ---------------- helpers ----------------
__device__ __forceinline__ uint32_t smem_u32(const void* p) {
    uint32_t a;
    asm("{ .reg .u64 t; cvta.to.shared.u64 t, %1; cvt.u32.u64 %0, t; }" : "=r"(a) : "l"(p));
    return a;
}
__device__ __forceinline__ uint32_t bf2u(float a, float b) {
    __nv_bfloat162 t = __floats2bfloat162_rn(a, b);
    return *reinterpret_cast<uint32_t*>(&t);
}

// ---------------- prep kernels ----------------
// w_last -> Wexp[4]: slots [w_hi, w_lo, w_hi, -w^3/6]
__global__ void prep_last_kernel(const float* __restrict__ w_last, __nv_bfloat16* __restrict__ out) {
    int idx = blockIdx.x * 256 + threadIdx.x;       // 0..65535
    float w = w_last[idx];
    int h = idx >> 8, k = idx & 255;
    __nv_bfloat16* o = out + (size_t)h * K1 + k;
    float hi = __bfloat162float(__float2bfloat16_rn(w));
    float lo = w - hi;
    o[0]   = __float2bfloat16_rn(hi);
    o[256] = __float2bfloat16_rn(lo);
    o[512] = __float2bfloat16_rn(hi);
    o[768] = __float2bfloat16_rn(-w * w * w * (1.0f / 6.0f));
}

// w1[l] -> A1 (split [hi,hi,lo], K=768) and A3 (plain bf16)
__global__ void prep_w1_kernel(const float* __restrict__ w1,
                               __nv_bfloat16* __restrict__ A1, __nv_bfloat16* __restrict__ A3) {
    int l = blockIdx.y;
    int idx = blockIdx.x * 256 + threadIdx.x;
    float w = w1[(size_t)l * 65536 + idx];
    int j = idx >> 8, h = idx & 255;
    float hi = __bfloat162float(__float2bfloat16_rn(w));
    float lo = w - hi;
    __nv_bfloat16* o = A1 + (size_t)l * HID * KW + (size_t)j * KW + h;
    o[0]   = __float2bfloat16_rn(hi);
    o[256] = __float2bfloat16_rn(hi);
    o[512] = __float2bfloat16_rn(lo);
    A3[(size_t)l * 65536 + idx] = __float2bfloat16_rn(w);
}

// Wsin_l transposed -> BT (split [hi,lo,hi], rows kk, cols h) and BT3 = (w^3/6)T
__global__ void prep_wsinT_kernel(const float* __restrict__ w0, const float* __restrict__ ws,
                                  __nv_bfloat16* __restrict__ BT, __nv_bfloat16* __restrict__ BT3) {
    __shared__ float t[32][33];
    int l = blockIdx.z;
    const float* src = (l == 0) ? w0 : ws + (size_t)(l - 1) * 65536;
    int h0 = blockIdx.y * 32, kk0 = blockIdx.x * 32;
    int x = threadIdx.x, y = threadIdx.y;          // 32 x 8
#pragma unroll
    for (int i = 0; i < 4; i++)
        t[y + i * 8][x] = src[(size_t)(h0 + y + i * 8) * 256 + kk0 + x];
    __syncthreads();
#pragma unroll
    for (int i = 0; i < 4; i++) {
        int kkoff = y + i * 8;
        float w = t[x][kkoff];                     // = Wsin[h0+x][kk0+kkoff]
        float hi = __bfloat162float(__float2bfloat16_rn(w));
        float lo = w - hi;
        __nv_bfloat16* o = BT + (size_t)l * HID * KW + (size_t)(kk0 + kkoff) * KW + h0 + x;
        o[0]   = __float2bfloat16_rn(hi);
        o[256] = __float2bfloat16_rn(lo);
        o[512] = __float2bfloat16_rn(hi);
        BT3[(size_t)l * 65536 + (size_t)(kk0 + kkoff) * 256 + h0 + x] =
            __float2bfloat16_rn(w * w * w * (1.0f / 6.0f));
    }
}

// ---------------- Fourier features -> expanded activations ----------------
__device__ __forceinline__ void write4(__nv_bfloat16* r, int j, float v) {
    float hi = __bfloat162float(__float2bfloat16_rn(v));
    float lo = v - hi;
    r[j]       = __float2bfloat16_rn(hi);
    r[256 + j] = __float2bfloat16_rn(hi);
    r[512 + j] = __float2bfloat16_rn(lo);
    r[768 + j] = __float2bfloat16_rn(v * v * v);
}
__global__ void fourier_kernel(const float* __restrict__ coords, const float* __restrict__ B,
                               __nv_bfloat16* __restrict__ X) {
    int m = blockIdx.x;       // 0..8191
    int f = threadIdx.x;      // 0..127
    float x0, x1, x2;
    if (m < 4096) {
        const float* c = coords + m * 6;
        x0 = c[0]; x1 = c[1]; x2 = c[2];
    } else {
        const float* c = coords + (m - 4096) * 6;
        x0 = c[3]; x1 = c[4]; x2 = c[5];
    }
    float p = x0 * __ldg(&B[f]) + x1 * __ldg(&B[128 + f]) + x2 * __ldg(&B[256 + f]);
    p *= 6.283185307179586f;
    __nv_bfloat16* r = X + (size_t)m * K1;
    write4(r, f, sinf(p));
    write4(r, 128 + f, cosf(p));
}

// ---------------- HMMA GEMM with fused epilogue ----------------
// D[m,n] = sum_k A[m,k]*B[n,k]  (both K-major), fp32 accum.
// CTA tile 64x128, 8 warps (warp 32x32), 4-stage cp.async, depth-2 prefetch,
// software-pipelined ldmatrix fragments. Batched via blockIdx.z strides.
// EPI 1: y = sin(D + bias[n]) -> 4-slot expansion (K1 layout)
// EPI 2: fp32 D -> out (HID row stride)
// EPI 3: hi/lo split of D -> Wexp slots [0]=hi [256]=lo [512]=hi (row stride 1024)
// EPI 4: -D -> Wexp slot 3 (offset 768, row stride 1024)
template <int KTOT, int EPI>
__global__ __launch_bounds__(256, 2)
void gemm_kernel(const __nv_bfloat16* __restrict__ A, const __nv_bfloat16* __restrict__ Bw,
                 const float* __restrict__ bias, void* __restrict__ outp,
                 size_t aBatch, size_t bBatch, size_t oBatch) {
    extern __shared__ char smem[];
    const uint32_t sb = smem_u32(smem);
    const int tid = threadIdx.x;
    const int lane = tid & 31;
    const int wid = tid >> 5;
    const int warp_m = wid & 1;     // 0..1 : 32-row slab
    const int warp_n = wid >> 1;    // 0..3 : 32-col slab
    const int m0 = blockIdx.x * TILE_M;
    const int n0 = blockIdx.y * TILE_N;
    A  += (size_t)blockIdx.z * aBatch;
    Bw += (size_t)blockIdx.z * bBatch;

    float acc[2][4][4];
#pragma unroll
    for (int i = 0; i < 2; i++)
#pragma unroll
        for (int j = 0; j < 4; j++)
#pragma unroll
            for (int e = 0; e < 4; e++) acc[i][j][e] = 0.f;

    constexpr int NCH = KTOT / KC;
    static_assert(NCH >= 3, "pipeline needs >= 3 chunks");

    auto issue_loads = [&](int c) {
        const int k0 = c * KC;
        const uint32_t dbase = sb + (uint32_t)(c % NSTAGE) * STAGE_BYTES;
#pragma unroll
        for (int i = 0; i < 2; i++) {              // A: 64 rows x 8 segs
            int idx = tid + i * 256;
            int r = idx >> 3, s8 = idx & 7;
            uint32_t off = (uint32_t)(r * 128 + ((s8 ^ (r & 7)) << 4));
            const void* srcA = A + (size_t)(m0 + r) * KTOT + k0 + s8 * 8;
            asm volatile("cp.async.cg.shared.global [%0], [%1], 16;"
                         :: "r"(dbase + off), "l"(srcA));
        }
#pragma unroll
        for (int i = 0; i < 4; i++) {              // B: 128 rows x 8 segs
            int idx = tid + i * 256;
            int r = idx >> 3, s8 = idx & 7;
            uint32_t off = (uint32_t)(r * 128 + ((s8 ^ (r & 7)) << 4));
            const void* srcB = Bw + (size_t)(n0 + r) * KTOT + k0 + s8 * 8;
            asm volatile("cp.async.cg.shared.global [%0], [%1], 16;"
                         :: "r"(dbase + STAGE_A + off), "l"(srcB));
        }
    };

    auto load_frags = [&](uint32_t sA, uint32_t sB, int ks,
                          uint32_t (*af)[4], uint32_t (*bfr)[4]) {
#pragma unroll
        for (int mi = 0; mi < 2; mi++) {
            int row = warp_m * 32 + mi * 16 + (lane & 15);
            int seg = ks * 2 + (lane >> 4);
            uint32_t ad = sA + (uint32_t)(row * 128 + ((seg ^ (row & 7)) << 4));
            asm volatile("ldmatrix.sync.aligned.m8n8.x4.shared.b16 {%0,%1,%2,%3}, [%4];"
                         : "=r"(af[mi][0]), "=r"(af[mi][1]), "=r"(af[mi][2]), "=r"(af[mi][3])
                         : "r"(ad));
        }
#pragma unroll
        for (int bi = 0; bi < 2; bi++) {
            int nrow = warp_n * 32 + bi * 16 + (lane & 7) + ((lane >> 4) << 3);
            int seg = ks * 2 + ((lane >> 3) & 1);
            uint32_t ad = sB + (uint32_t)(nrow * 128 + ((seg ^ (nrow & 7)) << 4));
            asm volatile("ldmatrix.sync.aligned.m8n8.x4.shared.b16 {%0,%1,%2,%3}, [%4];"
                         : "=r"(bfr[bi][0]), "=r"(bfr[bi][1]), "=r"(bfr[bi][2]), "=r"(bfr[bi][3])
                         : "r"(ad));
        }
    };

    issue_loads(0); asm volatile("cp.async.commit_group;");
    issue_loads(1); asm volatile("cp.async.commit_group;");
    issue_loads(2); asm volatile("cp.async.commit_group;");

    for (int c = 0; c < NCH; c++) {
        asm volatile("cp.async.wait_group 2;");
        __syncthreads();
        if (c + 3 < NCH) issue_loads(c + 3);
        asm volatile("cp.async.commit_group;");

        const uint32_t sA = sb + (uint32_t)(c % NSTAGE) * STAGE_BYTES;
        const uint32_t sB = sA + STAGE_A;

        uint32_t af[2][2][4], bf[2][2][4];
        load_frags(sA, sB, 0, af[0], bf[0]);
#pragma unroll
        for (int ks = 0; ks < 4; ks++) {
            if (ks < 3) load_frags(sA, sB, ks + 1, af[(ks + 1) & 1], bf[(ks + 1) & 1]);
            uint32_t (*a)[4] = af[ks & 1];
            uint32_t (*b)[4] = bf[ks & 1];
#pragma unroll
            for (int mi = 0; mi < 2; mi++)
#pragma unroll
                for (int ni = 0; ni < 4; ni++) {
                    uint32_t b0 = b[ni >> 1][(ni & 1) * 2];
                    uint32_t b1 = b[ni >> 1][(ni & 1) * 2 + 1];
                    asm volatile(
                        "mma.sync.aligned.m16n8k16.row.col.f32.bf16.bf16.f32 "
                        "{%0,%1,%2,%3}, {%4,%5,%6,%7}, {%8,%9}, {%0,%1,%2,%3};"
                        : "+f"(acc[mi][ni][0]), "+f"(acc[mi][ni][1]),
                          "+f"(acc[mi][ni][2]), "+f"(acc[mi][ni][3])
                        : "r"(a[mi][0]), "r"(a[mi][1]), "r"(a[mi][2]), "r"(a[mi][3]),
                          "r"(b0), "r"(b1));
                }
        }
    }

    // ---- epilogue ----
    const int q = lane >> 2;
    const int tq = lane & 3;
#pragma unroll
    for (int mi = 0; mi < 2; mi++) {
#pragma unroll
        for (int h = 0; h < 2; h++) {
            const int m = m0 + warp_m * 32 + mi * 16 + h * 8 + q;
#pragma unroll
            for (int ni = 0; ni < 4; ni++) {
                const int col = n0 + warp_n * 32 + ni * 8 + tq * 2;
                float v0 = acc[mi][ni][h * 2 + 0];
                float v1 = acc[mi][ni][h * 2 + 1];
                if (EPI == 1) {
                    __nv_bfloat16* d0 = (__nv_bfloat16*)outp + (size_t)m * K1 + col;
                    float z0 = v0 + __ldg(bias + col);
                    float z1 = v1 + __ldg(bias + col + 1);
                    float y0 = sinf(z0), y1 = sinf(z1);
                    float h0 = __bfloat162float(__float2bfloat16_rn(y0));
                    float h1 = __bfloat162float(__float2bfloat16_rn(y1));
                    uint32_t uh = bf2u(h0, h1);
                    *(uint32_t*)(d0)       = uh;
                    *(uint32_t*)(d0 + 256) = uh;
                    *(uint32_t*)(d0 + 512) = bf2u(y0 - h0, y1 - h1);
                    *(uint32_t*)(d0 + 768) = bf2u(y0 * y0 * y0, y1 * y1 * y1);
                } else if (EPI == 2) {
                    float* O = (float*)outp + (size_t)m * HID + col;
                    *reinterpret_cast<float2*>(O) = make_float2(v0, v1);
                } else if (EPI == 3) {
                    __nv_bfloat16* d0 = (__nv_bfloat16*)outp + (size_t)blockIdx.z * oBatch
                                        + (size_t)m * K1 + col;
                    float h0 = __bfloat162float(__float2bfloat16_rn(v0));
                    float h1 = __bfloat162float(__float2bfloat16_rn(v1));
                    uint32_t uh = bf2u(h0, h1);
                    *(uint32_t*)(d0)       = uh;
                    *(uint32_t*)(d0 + 256) = bf2u(v0 - h0, v1 - h1);
                    *(uint32_t*)(d0 + 512) = uh;
                } else {  // EPI == 4
                    __nv_bfloat16* d0 = (__nv_bfloat16*)outp + (size_t)blockIdx.z * oBatch
                                        + (size_t)m * K1 + 768 + col;
                    *(uint32_t*)(d0) = bf2u(-v0, -v1);
                }
            }
        }
    }
}

// coords passthrough (tuple element #2)
__global__ void copy_kernel(const float* __restrict__ src, float* __restrict__ dst, int n) {
    int i = blockIdx.x * blockDim.x + threadIdx.x;
    if (i < n) dst[i] = src[i];
}

extern "C" void kernel_launch(void* const* d_in, const int* in_sizes, int n_in,
                              void* d_out, int out_size) {
    const float* coords = (const float*)d_in[0];  // (4096, 6)
    const float* B      = (const float*)d_in[1];  // (3, 128)
    const float* w0     = (const float*)d_in[2];  // (256, 256)
    const float* ws     = (const float*)d_in[3];  // (3, 256, 256)
    const float* w_last = (const float*)d_in[4];  // (256, 256)
    const float* w1     = (const float*)d_in[5];  // (4, 256, 256)
    const float* b1     = (const float*)d_in[6];  // (4, 256)
    float* out = (float*)d_out;

    __nv_bfloat16 *XA, *XB, *Wexp, *A1, *A3, *BT, *BT3;
    cudaGetSymbolAddress((void**)&XA, g_XA);
    cudaGetSymbolAddress((void**)&XB, g_XB);
    cudaGetSymbolAddress((void**)&Wexp, g_Wexp);
    cudaGetSymbolAddress((void**)&A1, g_A1);
    cudaGetSymbolAddress((void**)&A3, g_A3);
    cudaGetSymbolAddress((void**)&BT, g_BT);
    cudaGetSymbolAddress((void**)&BT3, g_BT3);

    cudaFuncSetAttribute(gemm_kernel<K1, 1>, cudaFuncAttributeMaxDynamicSharedMemorySize, SMEM_TOTAL);
    cudaFuncSetAttribute(gemm_kernel<K1, 2>, cudaFuncAttributeMaxDynamicSharedMemorySize, SMEM_TOTAL);
    cudaFuncSetAttribute(gemm_kernel<KW, 3>, cudaFuncAttributeMaxDynamicSharedMemorySize, SMEM_TOTAL);
    cudaFuncSetAttribute(gemm_kernel<HID, 4>, cudaFuncAttributeMaxDynamicSharedMemorySize, SMEM_TOTAL);

    // ---- weight prep (every launch; deterministic) ----
    prep_w1_kernel<<<dim3(256, 4), 256>>>(w1, A1, A3);
    prep_wsinT_kernel<<<dim3(8, 8, 4), dim3(32, 8)>>>(w0, ws, BT, BT3);
    prep_last_kernel<<<256, 256>>>(w_last, Wexp + (size_t)4 * HID * K1);
    // C1 = W1@Wsin (split GEMM, K=768) -> Wexp slots 0..2, batched over 4 layers
    gemm_kernel<KW, 3><<<dim3(4, 2, 4), 256, SMEM_TOTAL>>>(
        A1, BT, nullptr, Wexp, (size_t)HID * KW, (size_t)HID * KW, (size_t)HID * K1);
    // C3 = W1@(Wsin^3/6) (K=256) -> Wexp slot 3 (negated)
    gemm_kernel<HID, 4><<<dim3(4, 2, 4), 256, SMEM_TOTAL>>>(
        A3, BT3, nullptr, Wexp, (size_t)HID * HID, (size_t)HID * HID, (size_t)HID * K1);

    // ---- network ----
    fourier_kernel<<<MROWS, 128>>>(coords, B, XA);

    const dim3 grid(MROWS / TILE_M, HID / TILE_N, 1);  // (128, 2)
    __nv_bfloat16* bufs[2] = { XA, XB };
    for (int l = 0; l < 4; l++) {
        gemm_kernel<K1, 1><<<grid, 256, SMEM_TOTAL>>>(
            bufs[l & 1], Wexp + (size_t)l * HID * K1, b1 + l * 256, bufs[(l + 1) & 1], 0, 0, 0);
    }
    gemm_kernel<K1, 2><<<grid, 256, SMEM_TOTAL>>>(
        XA, Wexp + (size_t)4 * HID * K1, nullptr, out, 0, 0, 0);
    copy_kernel<<<(NCOORD + 255) / 256, 256>>>(coords, out + (size_t)MROWS * HID, NCOORD);
}